// round 11
// baseline (speedup 1.0000x reference)
#include <cuda_runtime.h>

#define POOL 7
#define CELLS (POOL * POOL)
#define MAXSORT 2048
#define BINS 1024
#define SMS 148

__device__ unsigned int g_perm[MAXSORT];

__device__ __forceinline__ float4 lerp4(float4 tl, float4 tr, float4 bl, float4 br,
                                        float fx, float fy)
{
    float4 r;
    float tx = tl.x + (tr.x - tl.x) * fx;
    float ty = tl.y + (tr.y - tl.y) * fx;
    float tz = tl.z + (tr.z - tl.z) * fx;
    float tw = tl.w + (tr.w - tl.w) * fx;
    float bx = bl.x + (br.x - bl.x) * fx;
    float by = bl.y + (br.y - bl.y) * fx;
    float bz = bl.z + (br.z - bl.z) * fx;
    float bw = bl.w + (br.w - bl.w) * fx;
    r.x = tx + (bx - tx) * fy;
    r.y = ty + (by - ty) * fy;
    r.z = tz + (bz - tz) * fy;
    r.w = tw + (bw - tw) * fy;
    return r;
}

// ---- Kernel A: counting-sort boxes by (batch, level, Morton6) -> g_perm ----
// Permutation only decides WHICH CTA computes a box; per-box output values
// are order-independent -> deterministic result.
__global__ __launch_bounds__(1024) void bin_boxes_kernel(
    const float* __restrict__ boxes,
    const float* __restrict__ meta,
    int N, int NB)
{
    __shared__ int   hist[BINS];
    __shared__ int   pfx[BINS];
    __shared__ short sbin[MAXSORT];
    __shared__ short srank[MAXSORT];

    const int tid = threadIdx.x;
    for (int i = tid; i < BINS; i += 1024) hist[i] = 0;
    __syncthreads();

    float scale = 224.0f / sqrtf(meta[4] * meta[5]);

    for (int i = tid; i < NB; i += 1024) {
        const float* bx = boxes + (size_t)i * 4;
        float y1 = bx[0], x1 = bx[1], y2 = bx[2], x2 = bx[3];
        float h = y2 - y1, w = x2 - x1;
        float lvl = log2f(sqrtf(h * w) / scale);
        float rl  = 4.0f + rintf(lvl);
        rl = fminf(fmaxf(rl, 2.0f), 5.0f);
        int li = (int)rl - 2;
        int b  = i / N;
        float cy = (y1 + y2) * 0.5f;
        float cx = (x1 + x2) * 0.5f;
        int qy = min(7, max(0, (int)(cy * 8.0f)));
        int qx = min(7, max(0, (int)(cx * 8.0f)));
        int m6 = ((qy & 4) << 3) | ((qx & 4) << 2) | ((qy & 2) << 2)
               | ((qx & 2) << 1) | ((qy & 1) << 1) | (qx & 1);
        int bin = (((b << 2) | li) << 6) | m6;
        int r = atomicAdd(&hist[bin], 1);
        sbin[i]  = (short)bin;
        srank[i] = (short)r;
    }
    for (int i = NB + tid; i < MAXSORT; i += 1024)
        g_perm[i] = 0xFFFFFFFFu;
    __syncthreads();

    pfx[tid] = hist[tid];
    __syncthreads();
    for (int d = 1; d < BINS; d <<= 1) {
        int v   = pfx[tid];
        int add = (tid >= d) ? pfx[tid - d] : 0;
        __syncthreads();
        pfx[tid] = v + add;
        __syncthreads();
    }

    for (int i = tid; i < NB; i += 1024) {
        int bin = sbin[i];
        int pos = pfx[bin] - hist[bin] + srank[i];
        g_perm[pos] = (unsigned int)i;
    }
}

// ---- Kernel B: one box per 128-thread CTA, placement-aware bid->box map ----
// Classic placement: SM = LUT[bid % 148]. So sorted position
// p = (bid % 148) * W + bid / 148 gives each SM a CONTIGUOUS run of W
// Morton/level-sorted boxes -> resident CTAs on one SM share overlapping
// feature footprints -> L1 hits instead of L2 traffic.
__global__ __launch_bounds__(128, 16) void roialign_c256_kernel(
    const float* __restrict__ boxes,
    const float* __restrict__ meta,
    const float* __restrict__ f2,
    const float* __restrict__ f3,
    const float* __restrict__ f4,
    const float* __restrict__ f5,
    float* __restrict__ out,
    int N, int NB, int W)
{
    __shared__ int4   s_off[CELLS];
    __shared__ float2 s_f[CELLS];
    __shared__ const float4* s_base;
    __shared__ int s_bn;

    const int tid = threadIdx.x;

    if (tid == 0) {
        int p = (blockIdx.x % SMS) * W + blockIdx.x / SMS;
        int bn = (p < NB) ? (int)g_perm[p] : -1;
        if ((unsigned)bn >= (unsigned)NB) bn = -1;
        s_bn = bn;
    }
    __syncthreads();

    const int bn = s_bn;
    if (bn < 0) return;

    if (tid < CELLS) {
        const int b = bn / N;
        const float* bx = boxes + (size_t)bn * 4;
        float y1 = bx[0], x1 = bx[1], y2 = bx[2], x2 = bx[3];
        float h = y2 - y1, w = x2 - x1;

        float scale = 224.0f / sqrtf(meta[4] * meta[5]);
        float lvl = log2f(sqrtf(h * w) / scale);
        float rl  = 4.0f + rintf(lvl);                 // half-to-even
        rl = fminf(fmaxf(rl, 2.0f), 5.0f);
        int li = (int)rl - 2;
        int H  = 256 >> li;

        const float* fm = (li == 0) ? f2 : (li == 1) ? f3 : (li == 2) ? f4 : f5;
        const float* base = fm + (size_t)b * H * H * 256;

        int py = tid / POOL;
        int px = tid - py * POOL;

        float Hm1 = (float)(H - 1);
        float ys = y1 * Hm1 + (float)py * ((h * Hm1) / 6.0f);
        float xs = x1 * Hm1 + (float)px * ((w * Hm1) / 6.0f);

        float y0f = floorf(ys), x0f = floorf(xs);
        int y0  = min(max((int)y0f, 0), H - 1);
        int x0  = min(max((int)x0f, 0), H - 1);
        int y1i = min(y0 + 1, H - 1);
        int x1i = min(x0 + 1, H - 1);

        int4 off;
        off.x = (y0  * H + x0 ) * 64;
        off.y = (y0  * H + x1i) * 64;
        off.z = (y1i * H + x0 ) * 64;
        off.w = (y1i * H + x1i) * 64;
        s_off[tid] = off;
        s_f[tid] = make_float2(xs - x0f, ys - y0f);
        if (tid == 0) s_base = (const float4*)base;
    }
    __syncthreads();

    const float4* base = s_base;
    const int c4  = tid & 63;        // channel-quad
    const int grp = tid >> 6;        // 0..1

    float4* ob = (float4*)out + (size_t)bn * CELLS * 64 + c4;

    #pragma unroll 1
    for (int cell = grp; cell < CELLS; cell += 2) {
        int4   off = s_off[cell];
        float2 f   = s_f[cell];

        float4 tl = __ldg(base + off.x + c4);
        float4 tr = __ldg(base + off.y + c4);
        float4 bl = __ldg(base + off.z + c4);
        float4 br = __ldg(base + off.w + c4);

        __stcs(ob + cell * 64, lerp4(tl, tr, bl, br, f.x, f.y));
    }
}

// ---- generic fallback (any C divisible by 4, or NB > MAXSORT) ----

struct __align__(16) CellParam {
    const float4* tl; const float4* tr;
    const float4* bl; const float4* br;
    float fx, fy, pad0, pad1;
};

__global__ __launch_bounds__(256) void roialign_generic_kernel(
    const float* __restrict__ boxes, const float* __restrict__ meta,
    const float* __restrict__ f2, const float* __restrict__ f3,
    const float* __restrict__ f4, const float* __restrict__ f5,
    float* __restrict__ out, int N, int C)
{
    __shared__ CellParam cp[CELLS];
    const int bn  = blockIdx.x;
    const int tid = threadIdx.x;

    if (tid < CELLS) {
        const int b = bn / N;
        const float* bx = boxes + (size_t)bn * 4;
        float y1 = bx[0], x1 = bx[1], y2 = bx[2], x2 = bx[3];
        float h = y2 - y1, w = x2 - x1;
        float scale = 224.0f / sqrtf(meta[4] * meta[5]);
        float lvl = log2f(sqrtf(h * w) / scale);
        float rl  = 4.0f + rintf(lvl);
        rl = fminf(fmaxf(rl, 2.0f), 5.0f);
        int li = (int)rl - 2;
        int H  = 256 >> li;
        const float* fm = (li == 0) ? f2 : (li == 1) ? f3 : (li == 2) ? f4 : f5;
        const float* base = fm + (size_t)b * H * H * C;
        int py = tid / POOL;
        int px = tid - py * POOL;
        float Hm1 = (float)(H - 1);
        float ys = y1 * Hm1 + (float)py * ((h * Hm1) / 6.0f);
        float xs = x1 * Hm1 + (float)px * ((w * Hm1) / 6.0f);
        float y0f = floorf(ys), x0f = floorf(xs);
        int y0  = min(max((int)y0f, 0), H - 1);
        int x0  = min(max((int)x0f, 0), H - 1);
        int y1i = min(y0 + 1, H - 1);
        int x1i = min(x0 + 1, H - 1);
        CellParam p;
        p.tl = (const float4*)(base + (size_t)(y0  * H + x0 ) * C);
        p.tr = (const float4*)(base + (size_t)(y0  * H + x1i) * C);
        p.bl = (const float4*)(base + (size_t)(y1i * H + x0 ) * C);
        p.br = (const float4*)(base + (size_t)(y1i * H + x1i) * C);
        p.fx = xs - x0f;  p.fy = ys - y0f;
        p.pad0 = 0.f; p.pad1 = 0.f;
        cp[tid] = p;
    }
    __syncthreads();

    const int c4pc = C >> 2;
    const int c4   = tid % c4pc;
    const int cw   = tid / c4pc;
    const int cstr = blockDim.x / c4pc;
    float4* ob = (float4*)out + (size_t)bn * CELLS * c4pc;

    for (int cell = cw; cell < CELLS; cell += cstr) {
        float fx = cp[cell].fx, fy = cp[cell].fy;
        float4 tl = __ldg(cp[cell].tl + c4);
        float4 tr = __ldg(cp[cell].tr + c4);
        float4 bl = __ldg(cp[cell].bl + c4);
        float4 br = __ldg(cp[cell].br + c4);
        ob[cell * c4pc + c4] = lerp4(tl, tr, bl, br, fx, fy);
    }
}

extern "C" void kernel_launch(void* const* d_in, const int* in_sizes, int n_in,
                              void* d_out, int out_size) {
    const float* boxes = (const float*)d_in[0];
    const float* meta  = (const float*)d_in[1];
    const float* f2    = (const float*)d_in[2];
    const float* f3    = (const float*)d_in[3];
    const float* f4    = (const float*)d_in[4];
    const float* f5    = (const float*)d_in[5];
    float* out = (float*)d_out;

    int B  = in_sizes[1] / 14;
    int N  = in_sizes[0] / (4 * B);
    int C  = in_sizes[2] / (B * 256 * 256);
    int NB = B * N;

    if (C == 256 && NB <= MAXSORT && B <= 4) {
        bin_boxes_kernel<<<1, 1024>>>(boxes, meta, N, NB);
        int W = (NB + SMS - 1) / SMS;          // boxes per SM group
        roialign_c256_kernel<<<SMS * W, 128>>>(boxes, meta, f2, f3, f4, f5,
                                               out, N, NB, W);
    } else {
        roialign_generic_kernel<<<NB, 256>>>(boxes, meta, f2, f3, f4, f5, out, N, C);
    }
}